// round 9
// baseline (speedup 1.0000x reference)
#include <cuda_runtime.h>
#include <cuda_bf16.h>
#include <cuda_fp16.h>
#include <math.h>
#include <stdint.h>

// Problem constants (fixed by the dataset)
#define NMAX 100000
#define EMAX 1600000
#define F    128
#define G    64
#define OUTD 10

// ---------------- device scratch (static, no allocation) ----------------
__device__ float   g_bufA[(size_t)NMAX * F];   // GEMM output h = x @ W (fp32)
__device__ __half2 g_bufA16[(size_t)NMAX * 64];// GEMM output h (fp16, for gathers)
__device__ float   g_bufB[(size_t)NMAX * F];   // aggregation output / next layer input
__device__ float   g_dinv[NMAX];
__device__ int     g_deg[NMAX];                // degree incl. self loop
__device__ int     g_scan[NMAX];               // per-block inclusive scan of (deg-1)
__device__ int     g_bsum[128];                // block sums -> exclusive offsets
__device__ int     g_rowstart[NMAX];           // CSR row start (real edges only)
__device__ int     g_pos[NMAX];                // fill cursor
__device__ float2  g_edge[EMAX];               // packed (src as int bits, norm)
__device__ float   g_gsum[G * F];
__device__ int     g_gcnt[G];

__device__ __forceinline__ int clampi(int v, int lo, int hi) {
    return v < lo ? lo : (v > hi ? hi : v);
}

__device__ __forceinline__ uint32_t f2tf32(float x) {
    uint32_t r;
    asm("cvt.rna.tf32.f32 %0, %1;" : "=r"(r) : "f"(x));
    return r;
}

__device__ __forceinline__ void mma_tf32(float* c, const uint32_t* a,
                                         uint32_t b0, uint32_t b1) {
    asm volatile(
        "mma.sync.aligned.m16n8k8.row.col.f32.tf32.tf32.f32 "
        "{%0,%1,%2,%3},{%4,%5,%6,%7},{%8,%9},{%0,%1,%2,%3};"
        : "+f"(c[0]), "+f"(c[1]), "+f"(c[2]), "+f"(c[3])
        : "r"(a[0]), "r"(a[1]), "r"(a[2]), "r"(a[3]), "r"(b0), "r"(b1));
}

// ---------------- degree ----------------
__global__ void k_deg_init(int n) {
    int i = blockIdx.x * blockDim.x + threadIdx.x;
    if (i < n) g_deg[i] = 1;            // self loop contributes 1
}

__global__ void k_deg_count(const int* __restrict__ dst, int e, int n) {
    int i = blockIdx.x * blockDim.x + threadIdx.x;
    if (i < e) atomicAdd(&g_deg[clampi(dst[i], 0, n - 1)], 1);
}

// ---------------- scan1 (+dinv fused) ----------------
__global__ void k_scan1(int n) {                 // 1024 threads/block
    __shared__ int sh[1024];
    int gid = blockIdx.x * 1024 + threadIdx.x;
    int deg = (gid < n) ? g_deg[gid] : 1;
    if (gid < n) g_dinv[gid] = rsqrtf((float)deg);
    int v = (gid < n) ? (deg - 1) : 0;
    sh[threadIdx.x] = v;
    __syncthreads();
    for (int off = 1; off < 1024; off <<= 1) {   // Hillis-Steele inclusive
        int t = (threadIdx.x >= off) ? sh[threadIdx.x - off] : 0;
        __syncthreads();
        sh[threadIdx.x] += t;
        __syncthreads();
    }
    if (gid < n) g_scan[gid] = sh[threadIdx.x];
    if (threadIdx.x == 1023) g_bsum[blockIdx.x] = sh[1023];
}

// ---------------- scan2 (+pool_init fused) ----------------
__global__ void k_scan2(int nb, const int* __restrict__ batch, int n) {  // 1 block, 128 thr
    __shared__ int sh[128];
    int t = threadIdx.x;
    sh[t] = (t < nb) ? g_bsum[t] : 0;
    __syncthreads();
    if (t == 0) {
        int acc = 0;
        for (int i = 0; i < nb; i++) { int v = sh[i]; sh[i] = acc; acc += v; }
    }
    __syncthreads();
    if (t < nb) g_bsum[t] = sh[t];

    // pool init
    for (int i = t; i < G * F; i += blockDim.x) g_gsum[i] = 0.f;
    if (t < G) {
        int lo, hi;
        {
            int a = 0, b = n;
            while (a < b) { int m = (a + b) >> 1; if (batch[m] < t) a = m + 1; else b = m; }
            lo = a;
        }
        {
            int a = 0, b = n;
            while (a < b) { int m = (a + b) >> 1; if (batch[m] < t + 1) a = m + 1; else b = m; }
            hi = a;
        }
        g_gcnt[t] = hi - lo;
    }
}

__global__ void k_scan3(int n) {
    int gid = blockIdx.x * blockDim.x + threadIdx.x;
    if (gid >= n) return;
    int cnt   = g_deg[gid] - 1;
    int start = g_scan[gid] - cnt + g_bsum[gid >> 10];   // exclusive start
    g_rowstart[gid] = start;
    g_pos[gid]      = start;
}

__global__ void k_csr_fill(const int* __restrict__ src, const int* __restrict__ dst,
                           int e, int n) {
    int i = blockIdx.x * blockDim.x + threadIdx.x;
    if (i >= e) return;
    int s = clampi(src[i], 0, n - 1);
    int d = clampi(dst[i], 0, n - 1);
    int slot = atomicAdd(&g_pos[d], 1);
    g_edge[slot] = make_float2(__int_as_float(s), g_dinv[s] * g_dinv[d]);
}

// ---------------- TF32 tensor-core GEMM (3xTF32 split, ~fp32 accuracy) ---------
// g_bufA[n x 128] = X[n x 128] @ W[128 x 128]; also writes fp16 copy g_bufA16.
// Block: 256 threads (8 warps), tile 128 rows x 128 cols; warp tile 32x64.
#define SAS 136
__global__ __launch_bounds__(256) void k_gemm_tf32(
    const float* __restrict__ Xext, int use_ext,
    const float* __restrict__ W, int nrows)
{
    const float* X = use_ext ? Xext : (const float*)g_bufB;
    float*       Y = g_bufA;

    __shared__ uint32_t sAh[16 * SAS];   // A^T hi : [k][m]
    __shared__ uint32_t sAl[16 * SAS];   // A^T lo
    __shared__ uint32_t sBh[16 * SAS];   // W hi   : [k][n]
    __shared__ uint32_t sBl[16 * SAS];   // W lo

    int tid  = threadIdx.x;
    int row0 = blockIdx.x * 128;
    int lane = tid & 31;
    int wid  = tid >> 5;
    int g    = lane >> 2;          // 0..7
    int t    = lane & 3;           // 0..3
    int wm   = (wid & 3) * 32;     // warp m offset: 0,32,64,96
    int wn   = (wid >> 2) * 64;    // warp n offset: 0,64

    float acc[2][8][4];
#pragma unroll
    for (int mi = 0; mi < 2; mi++)
#pragma unroll
        for (int ni = 0; ni < 8; ni++)
#pragma unroll
            for (int q = 0; q < 4; q++) acc[mi][ni][q] = 0.f;

    for (int kt = 0; kt < 128; kt += 16) {
        // ---- fill A^T tile: sA[k][m] = X[row0+m][kt+k], split hi/lo ----
#pragma unroll
        for (int h = 0; h < 2; h++) {
            int f  = tid + h * 256;                 // 0..511 float4 slots
            int c4 = (f >> 5) & 3;                  // k group (0..3)
            int r  = (f & 31) + ((f >> 7) << 5);    // m row (0..127)
            int row = row0 + r;
            float4 v = make_float4(0.f, 0.f, 0.f, 0.f);
            if (row < nrows) v = *(const float4*)(X + (size_t)row * 128 + kt + c4 * 4);
            float xs[4] = {v.x, v.y, v.z, v.w};
#pragma unroll
            for (int i = 0; i < 4; i++) {
                uint32_t hi = f2tf32(xs[i]);
                uint32_t lo = f2tf32(xs[i] - __uint_as_float(hi));
                sAh[(c4 * 4 + i) * SAS + r] = hi;
                sAl[(c4 * 4 + i) * SAS + r] = lo;
            }
        }
        // ---- fill W tile: sB[k][n] = W[kt+k][n], split hi/lo ----
#pragma unroll
        for (int h = 0; h < 2; h++) {
            int f = tid + h * 256;                  // 0..511
            int k = f >> 5;                         // 0..15
            int c = (f & 31) * 4;                   // 0..124
            float4 v = *(const float4*)(W + (size_t)(kt + k) * 128 + c);
            float xs[4] = {v.x, v.y, v.z, v.w};
#pragma unroll
            for (int i = 0; i < 4; i++) {
                uint32_t hi = f2tf32(xs[i]);
                uint32_t lo = f2tf32(xs[i] - __uint_as_float(hi));
                sBh[k * SAS + c + i] = hi;
                sBl[k * SAS + c + i] = lo;
            }
        }
        __syncthreads();

#pragma unroll
        for (int k0 = 0; k0 < 16; k0 += 8) {
            uint32_t ah[2][4], al[2][4];
#pragma unroll
            for (int mi = 0; mi < 2; mi++) {
                int m = wm + mi * 16;
                ah[mi][0] = sAh[(k0 + t) * SAS + m + g];
                ah[mi][1] = sAh[(k0 + t) * SAS + m + g + 8];
                ah[mi][2] = sAh[(k0 + t + 4) * SAS + m + g];
                ah[mi][3] = sAh[(k0 + t + 4) * SAS + m + g + 8];
                al[mi][0] = sAl[(k0 + t) * SAS + m + g];
                al[mi][1] = sAl[(k0 + t) * SAS + m + g + 8];
                al[mi][2] = sAl[(k0 + t + 4) * SAS + m + g];
                al[mi][3] = sAl[(k0 + t + 4) * SAS + m + g + 8];
            }
#pragma unroll
            for (int ni = 0; ni < 8; ni++) {
                int n = wn + ni * 8 + g;
                uint32_t bh0 = sBh[(k0 + t) * SAS + n];
                uint32_t bh1 = sBh[(k0 + t + 4) * SAS + n];
                uint32_t bl0 = sBl[(k0 + t) * SAS + n];
                uint32_t bl1 = sBl[(k0 + t + 4) * SAS + n];
#pragma unroll
                for (int mi = 0; mi < 2; mi++) {
                    mma_tf32(acc[mi][ni], ah[mi], bh0, bh1);   // hi*hi
                    mma_tf32(acc[mi][ni], al[mi], bh0, bh1);   // lo*hi
                    mma_tf32(acc[mi][ni], ah[mi], bl0, bl1);   // hi*lo
                }
            }
        }
        __syncthreads();
    }

    // ---- write C fragments (fp32 + fp16 copy) ----
#pragma unroll
    for (int mi = 0; mi < 2; mi++) {
#pragma unroll
        for (int ni = 0; ni < 8; ni++) {
            int col = wn + ni * 8 + t * 2;          // even
            int r0  = row0 + wm + mi * 16 + g;
            int r1  = r0 + 8;
            float2 v0 = make_float2(acc[mi][ni][0], acc[mi][ni][1]);
            float2 v1 = make_float2(acc[mi][ni][2], acc[mi][ni][3]);
            if (r0 < nrows) {
                *(float2*)(Y + (size_t)r0 * 128 + col) = v0;
                g_bufA16[(size_t)r0 * 64 + (col >> 1)] = __float22half2_rn(v0);
            }
            if (r1 < nrows) {
                *(float2*)(Y + (size_t)r1 * 128 + col) = v1;
                g_bufA16[(size_t)r1 * 64 + (col >> 1)] = __float22half2_rn(v1);
            }
        }
    }
}

// ---- fused aggregate: bufB[d] = prelu(dinv2*bufA[d] + sum norm*h16[s] + bias) ----
// Warp per dst node; lane owns 4 features. Self term fp32, gathers fp16.
// Depth-2 software pipeline: row-load consumes edge fetched one iteration earlier.
__device__ __forceinline__ uint2 row_ld(const __half2* base, int s, int lane) {
    return __ldg((const uint2*)(base + (size_t)s * 64) + lane);
}

__device__ __forceinline__ void fma_row(float4& acc, float nv, uint2 h) {
    float2 p0 = __half22float2(*(const __half2*)&h.x);
    float2 p1 = __half22float2(*(const __half2*)&h.y);
    acc.x = fmaf(nv, p0.x, acc.x);
    acc.y = fmaf(nv, p0.y, acc.y);
    acc.z = fmaf(nv, p1.x, acc.z);
    acc.w = fmaf(nv, p1.y, acc.w);
}

__global__ void k_aggregate(const float* __restrict__ bias,
                            const float* __restrict__ aP, int n, int do_prelu)
{
    int gw   = (blockIdx.x * blockDim.x + threadIdx.x) >> 5;
    int lane = threadIdx.x & 31;
    if (gw >= n) return;

    int   start = g_rowstart[gw];
    int   cnt   = g_deg[gw] - 1;
    float dv    = g_dinv[gw];
    const __half2* H16 = g_bufA16;

    float4 acc = *((const float4*)(g_bufA + (size_t)gw * 128) + lane);
    float  sc  = dv * dv;
    acc.x *= sc; acc.y *= sc; acc.z *= sc; acc.w *= sc;

    if (cnt > 0) {
        float2 e0 = g_edge[start];
        uint2  h0 = row_ld(H16, __float_as_int(e0.x), lane);
        if (cnt >= 2) {
            float2 e1 = g_edge[start + 1];
            int k = 0;
            for (; k + 2 < cnt; k++) {
                uint2  h1 = row_ld(H16, __float_as_int(e1.x), lane);  // e1 ready
                float2 e2 = g_edge[start + k + 2];                    // prefetch
                fma_row(acc, e0.y, h0);
                e0 = e1; h0 = h1; e1 = e2;
            }
            uint2 h1 = row_ld(H16, __float_as_int(e1.x), lane);
            fma_row(acc, e0.y, h0);
            e0 = e1; h0 = h1;
        }
        fma_row(acc, e0.y, h0);
    }

    float4 b = *((const float4*)bias + lane);
    acc.x += b.x; acc.y += b.y; acc.z += b.z; acc.w += b.w;

    if (do_prelu) {
        float al = aP[0];
        acc.x = acc.x > 0.f ? acc.x : al * acc.x;
        acc.y = acc.y > 0.f ? acc.y : al * acc.y;
        acc.z = acc.z > 0.f ? acc.z : al * acc.z;
        acc.w = acc.w > 0.f ? acc.w : al * acc.w;
    }
    *((float4*)(g_bufB + (size_t)gw * 128) + lane) = acc;
}

// ---------------- pooling ----------------
// 128 threads per block (one per feature); each block handles 256 nodes.
__global__ void k_pool_sum(const int* __restrict__ batch, int n) {
    int f  = threadIdx.x;                      // 0..127
    int n0 = blockIdx.x * 256;
    int n1 = min(n0 + 256, n);
    int gc = -1;
    float acc = 0.f;
    const float* H = g_bufB;
    for (int nn = n0; nn < n1; nn++) {
        int g = clampi(batch[nn], 0, G - 1);
        if (g != gc) {
            if (gc >= 0) atomicAdd(&g_gsum[gc * F + f], acc);
            acc = 0.f;
            gc = g;
        }
        acc += H[(size_t)nn * F + f];
    }
    if (gc >= 0) atomicAdd(&g_gsum[gc * F + f], acc);
}

__global__ void k_head(const float* __restrict__ linW, const float* __restrict__ linb,
                       float* __restrict__ out) {
    int t = blockIdx.x * blockDim.x + threadIdx.x;     // 640 outputs
    if (t >= G * OUTD) return;
    int g = t / OUTD;
    int o = t % OUTD;
    float c   = fmaxf((float)g_gcnt[g], 1.f);
    float inv = 1.f / c;
    float acc = 0.f;
#pragma unroll 8
    for (int h = 0; h < F; h++)
        acc = fmaf(g_gsum[g * F + h], linW[h * OUTD + o], acc);
    out[t] = acc * inv + linb[o];
}

// ---------------- launch ----------------
extern "C" void kernel_launch(void* const* d_in, const int* in_sizes, int n_in,
                              void* d_out, int out_size)
{
    // Resolve inputs BY SIZE (ordering-proof). Same-shaped tensors keep order.
    int iX = 0, iE = 0, iB = 0, iLW = 0, iLb = 0;
    int iW[3] = {0, 0, 0}, ib[3] = {0, 0, 0}, ia[2] = {0, 0};
    int nW = 0, nb = 0, na = 0;
    for (int i = 0; i < n_in; i++) {
        int s = in_sizes[i];
        if      (s == NMAX * F)   iX = i;
        else if (s == 2 * EMAX)   iE = i;
        else if (s == NMAX)       iB = i;
        else if (s == F * F)      { if (nW < 3) iW[nW++] = i; }
        else if (s == F)          { if (nb < 3) ib[nb++] = i; }
        else if (s == 1)          { if (na < 2) ia[na++] = i; }
        else if (s == F * OUTD)   iLW = i;
        else if (s == OUTD)       iLb = i;
    }

    const float* x    = (const float*)d_in[iX];
    const int*   ei   = (const int*)d_in[iE];    // int32 (JAX x64 disabled)
    const int*   bat  = (const int*)d_in[iB];
    const float* W0   = (const float*)d_in[iW[0]];
    const float* b0   = (const float*)d_in[ib[0]];
    const float* a0   = (const float*)d_in[ia[0]];
    const float* W1   = (const float*)d_in[iW[1]];
    const float* b1   = (const float*)d_in[ib[1]];
    const float* a1   = (const float*)d_in[ia[1]];
    const float* W2   = (const float*)d_in[iW[2]];
    const float* b2   = (const float*)d_in[ib[2]];
    const float* linW = (const float*)d_in[iLW];
    const float* linb = (const float*)d_in[iLb];
    float*       out  = (float*)d_out;

    int n = in_sizes[iX] / F;       // 100000
    int e = in_sizes[iE] / 2;       // 1600000
    const int* src = ei;
    const int* dst = ei + e;

    int nscan       = (n + 1023) / 1024;            // 98
    int gemm_blocks = (n + 127) / 128;
    int agg_blocks  = (n * 32 + 255) / 256;         // warp per node

    // launch index:                                              v
    k_deg_init <<<(n + 255) / 256, 256>>>(n);                  // 0
    k_deg_count<<<(e + 255) / 256, 256>>>(dst, e, n);          // 1
    k_scan1    <<<nscan, 1024>>>(n);                           // 2 (+dinv)
    k_gemm_tf32<<<gemm_blocks, 256>>>(x, 1, W0, n);            // 3  <-- ncu capture slot
    k_scan2    <<<1, 128>>>(nscan, bat, n);                    // 4 (+pool_init)
    k_scan3    <<<(n + 255) / 256, 256>>>(n);                  // 5
    k_csr_fill <<<(e + 255) / 256, 256>>>(src, dst, e, n);     // 6

    k_aggregate<<<agg_blocks, 256>>>(b0, a0, n, 1);            // 7
    k_gemm_tf32<<<gemm_blocks, 256>>>(nullptr, 0, W1, n);      // 8
    k_aggregate<<<agg_blocks, 256>>>(b1, a1, n, 1);            // 9
    k_gemm_tf32<<<gemm_blocks, 256>>>(nullptr, 0, W2, n);      // 10
    k_aggregate<<<agg_blocks, 256>>>(b2, nullptr, n, 0);       // 11

    k_pool_sum<<<(n + 255) / 256, 128>>>(bat, n);              // 12
    k_head<<<3, 256>>>(linW, linb, out);                       // 13
}

// round 11
// speedup vs baseline: 1.1021x; 1.1021x over previous
// R11 = R10 resubmitted verbatim (round 10 was a broker/container failure;
// the interleaved-LDS GEMM + aggregate revert never got measured).
#include <cuda_runtime.h>
#include <cuda_bf16.h>
#include <cuda_fp16.h>
#include <math.h>
#include <stdint.h>

// Problem constants (fixed by the dataset)
#define NMAX 100000
#define EMAX 1600000
#define F    128
#define G    64
#define OUTD 10

// ---------------- device scratch (static, no allocation) ----------------
__device__ float   g_bufA[(size_t)NMAX * F];   // GEMM output h = x @ W (fp32)
__device__ __half2 g_bufA16[(size_t)NMAX * 64];// GEMM output h (fp16, for gathers)
__device__ float   g_bufB[(size_t)NMAX * F];   // aggregation output / next layer input
__device__ float   g_dinv[NMAX];
__device__ int     g_deg[NMAX];                // degree incl. self loop
__device__ int     g_scan[NMAX];               // per-block inclusive scan of (deg-1)
__device__ int     g_bsum[128];                // block sums -> exclusive offsets
__device__ int     g_rowstart[NMAX];           // CSR row start (real edges only)
__device__ int     g_pos[NMAX];                // fill cursor
__device__ float2  g_edge[EMAX];               // packed (src as int bits, norm)
__device__ float   g_gsum[G * F];
__device__ int     g_gcnt[G];

__device__ __forceinline__ int clampi(int v, int lo, int hi) {
    return v < lo ? lo : (v > hi ? hi : v);
}

__device__ __forceinline__ uint32_t f2tf32(float x) {
    uint32_t r;
    asm("cvt.rna.tf32.f32 %0, %1;" : "=r"(r) : "f"(x));
    return r;
}

__device__ __forceinline__ uint2 split_tf32(float x) {
    uint32_t hi = f2tf32(x);
    uint32_t lo = f2tf32(x - __uint_as_float(hi));
    return make_uint2(hi, lo);
}

__device__ __forceinline__ void mma_tf32(float* c, const uint32_t* a,
                                         uint32_t b0, uint32_t b1) {
    asm volatile(
        "mma.sync.aligned.m16n8k8.row.col.f32.tf32.tf32.f32 "
        "{%0,%1,%2,%3},{%4,%5,%6,%7},{%8,%9},{%0,%1,%2,%3};"
        : "+f"(c[0]), "+f"(c[1]), "+f"(c[2]), "+f"(c[3])
        : "r"(a[0]), "r"(a[1]), "r"(a[2]), "r"(a[3]), "r"(b0), "r"(b1));
}

// ---------------- degree ----------------
__global__ void k_deg_init(int n) {
    int i = blockIdx.x * blockDim.x + threadIdx.x;
    if (i < n) g_deg[i] = 1;            // self loop contributes 1
}

__global__ void k_deg_count(const int* __restrict__ dst, int e, int n) {
    int i = blockIdx.x * blockDim.x + threadIdx.x;
    if (i < e) atomicAdd(&g_deg[clampi(dst[i], 0, n - 1)], 1);
}

// ---------------- scan1 (+dinv fused) ----------------
__global__ void k_scan1(int n) {                 // 1024 threads/block
    __shared__ int sh[1024];
    int gid = blockIdx.x * 1024 + threadIdx.x;
    int deg = (gid < n) ? g_deg[gid] : 1;
    if (gid < n) g_dinv[gid] = rsqrtf((float)deg);
    int v = (gid < n) ? (deg - 1) : 0;
    sh[threadIdx.x] = v;
    __syncthreads();
    for (int off = 1; off < 1024; off <<= 1) {   // Hillis-Steele inclusive
        int t = (threadIdx.x >= off) ? sh[threadIdx.x - off] : 0;
        __syncthreads();
        sh[threadIdx.x] += t;
        __syncthreads();
    }
    if (gid < n) g_scan[gid] = sh[threadIdx.x];
    if (threadIdx.x == 1023) g_bsum[blockIdx.x] = sh[1023];
}

// ---------------- scan2 (+pool_init fused) ----------------
__global__ void k_scan2(int nb, const int* __restrict__ batch, int n) {  // 1 block, 128 thr
    __shared__ int sh[128];
    int t = threadIdx.x;
    sh[t] = (t < nb) ? g_bsum[t] : 0;
    __syncthreads();
    if (t == 0) {
        int acc = 0;
        for (int i = 0; i < nb; i++) { int v = sh[i]; sh[i] = acc; acc += v; }
    }
    __syncthreads();
    if (t < nb) g_bsum[t] = sh[t];

    // pool init
    for (int i = t; i < G * F; i += blockDim.x) g_gsum[i] = 0.f;
    if (t < G) {
        int lo, hi;
        {
            int a = 0, b = n;
            while (a < b) { int m = (a + b) >> 1; if (batch[m] < t) a = m + 1; else b = m; }
            lo = a;
        }
        {
            int a = 0, b = n;
            while (a < b) { int m = (a + b) >> 1; if (batch[m] < t + 1) a = m + 1; else b = m; }
            hi = a;
        }
        g_gcnt[t] = hi - lo;
    }
}

__global__ void k_scan3(int n) {
    int gid = blockIdx.x * blockDim.x + threadIdx.x;
    if (gid >= n) return;
    int cnt   = g_deg[gid] - 1;
    int start = g_scan[gid] - cnt + g_bsum[gid >> 10];   // exclusive start
    g_rowstart[gid] = start;
    g_pos[gid]      = start;
}

__global__ void k_csr_fill(const int* __restrict__ src, const int* __restrict__ dst,
                           int e, int n) {
    int i = blockIdx.x * blockDim.x + threadIdx.x;
    if (i >= e) return;
    int s = clampi(src[i], 0, n - 1);
    int d = clampi(dst[i], 0, n - 1);
    int slot = atomicAdd(&g_pos[d], 1);
    g_edge[slot] = make_float2(__int_as_float(s), g_dinv[s] * g_dinv[d]);
}

// ---------------- TF32 tensor-core GEMM (3xTF32 split, ~fp32 accuracy) ---------
// g_bufA[n x 128] = X[n x 128] @ W[128 x 128]; also writes fp16 copy g_bufA16.
// Block: 256 threads (8 warps), tile 128 rows x 128 cols; warp tile 32x64.
// smem stores interleaved {hi,lo} uint2 pairs: fragment loads are LDS.64.
#define SA2 132            // uint2 per k-row (128 + 4 pad) => 1056 B/row
__global__ __launch_bounds__(256) void k_gemm_tf32(
    const float* __restrict__ Xext, int use_ext,
    const float* __restrict__ W, int nrows)
{
    const float* X = use_ext ? Xext : (const float*)g_bufB;
    float*       Y = g_bufA;

    __shared__ uint2 sA[16 * SA2];   // A^T {hi,lo} : [k][m]
    __shared__ uint2 sB[16 * SA2];   // W   {hi,lo} : [k][n]

    int tid  = threadIdx.x;
    int row0 = blockIdx.x * 128;
    int lane = tid & 31;
    int wid  = tid >> 5;
    int g    = lane >> 2;          // 0..7
    int t    = lane & 3;           // 0..3
    int wm   = (wid & 3) * 32;     // warp m offset: 0,32,64,96
    int wn   = (wid >> 2) * 64;    // warp n offset: 0,64

    float acc[2][8][4];
#pragma unroll
    for (int mi = 0; mi < 2; mi++)
#pragma unroll
        for (int ni = 0; ni < 8; ni++)
#pragma unroll
            for (int q = 0; q < 4; q++) acc[mi][ni][q] = 0.f;

    for (int kt = 0; kt < 128; kt += 16) {
        // ---- fill A^T tile: sA[k][m] = split(X[row0+m][kt+k]) ----
#pragma unroll
        for (int h = 0; h < 2; h++) {
            int f  = tid + h * 256;                 // 0..511 float4 slots
            int c4 = (f >> 5) & 3;                  // k group (0..3)
            int r  = (f & 31) + ((f >> 7) << 5);    // m row (0..127)
            int row = row0 + r;
            float4 v = make_float4(0.f, 0.f, 0.f, 0.f);
            if (row < nrows) v = *(const float4*)(X + (size_t)row * 128 + kt + c4 * 4);
            sA[(c4 * 4 + 0) * SA2 + r] = split_tf32(v.x);
            sA[(c4 * 4 + 1) * SA2 + r] = split_tf32(v.y);
            sA[(c4 * 4 + 2) * SA2 + r] = split_tf32(v.z);
            sA[(c4 * 4 + 3) * SA2 + r] = split_tf32(v.w);
        }
        // ---- fill W tile: sB[k][n] = split(W[kt+k][n]) ----
#pragma unroll
        for (int h = 0; h < 2; h++) {
            int f = tid + h * 256;                  // 0..511
            int k = f >> 5;                         // 0..15
            int c = (f & 31) * 4;                   // 0..124
            float4 v = *(const float4*)(W + (size_t)(kt + k) * 128 + c);
            sB[k * SA2 + c + 0] = split_tf32(v.x);
            sB[k * SA2 + c + 1] = split_tf32(v.y);
            sB[k * SA2 + c + 2] = split_tf32(v.z);
            sB[k * SA2 + c + 3] = split_tf32(v.w);
        }
        __syncthreads();

#pragma unroll
        for (int k0 = 0; k0 < 16; k0 += 8) {
            uint32_t ah[2][4], al[2][4];
#pragma unroll
            for (int mi = 0; mi < 2; mi++) {
                int m = wm + mi * 16;
                uint2 p0 = sA[(k0 + t) * SA2 + m + g];
                uint2 p1 = sA[(k0 + t) * SA2 + m + g + 8];
                uint2 p2 = sA[(k0 + t + 4) * SA2 + m + g];
                uint2 p3 = sA[(k0 + t + 4) * SA2 + m + g + 8];
                ah[mi][0] = p0.x; al[mi][0] = p0.y;
                ah[mi][1] = p1.x; al[mi][1] = p1.y;
                ah[mi][2] = p2.x; al[mi][2] = p2.y;
                ah[mi][3] = p3.x; al[mi][3] = p3.y;
            }
#pragma unroll
            for (int ni = 0; ni < 8; ni++) {
                int n = wn + ni * 8 + g;
                uint2 q0 = sB[(k0 + t) * SA2 + n];       // {bh0, bl0}
                uint2 q1 = sB[(k0 + t + 4) * SA2 + n];   // {bh1, bl1}
#pragma unroll
                for (int mi = 0; mi < 2; mi++) {
                    mma_tf32(acc[mi][ni], ah[mi], q0.x, q1.x);   // hi*hi
                    mma_tf32(acc[mi][ni], al[mi], q0.x, q1.x);   // lo*hi
                    mma_tf32(acc[mi][ni], ah[mi], q0.y, q1.y);   // hi*lo
                }
            }
        }
        __syncthreads();
    }

    // ---- write C fragments (fp32 + fp16 copy) ----
#pragma unroll
    for (int mi = 0; mi < 2; mi++) {
#pragma unroll
        for (int ni = 0; ni < 8; ni++) {
            int col = wn + ni * 8 + t * 2;          // even
            int r0  = row0 + wm + mi * 16 + g;
            int r1  = r0 + 8;
            float2 v0 = make_float2(acc[mi][ni][0], acc[mi][ni][1]);
            float2 v1 = make_float2(acc[mi][ni][2], acc[mi][ni][3]);
            if (r0 < nrows) {
                *(float2*)(Y + (size_t)r0 * 128 + col) = v0;
                g_bufA16[(size_t)r0 * 64 + (col >> 1)] = __float22half2_rn(v0);
            }
            if (r1 < nrows) {
                *(float2*)(Y + (size_t)r1 * 128 + col) = v1;
                g_bufA16[(size_t)r1 * 64 + (col >> 1)] = __float22half2_rn(v1);
            }
        }
    }
}

// ---- fused aggregate: bufB[d] = prelu(dinv2*bufA[d] + sum norm*h16[s] + bias) ----
// Warp per dst node; lane owns 4 features. Self term fp32, gathers fp16.
// (R8 version — depth-1 prefetch; the R9 deeper pipeline regressed.)
__global__ void k_aggregate(const float* __restrict__ bias,
                            const float* __restrict__ aP, int n, int do_prelu)
{
    int gw   = (blockIdx.x * blockDim.x + threadIdx.x) >> 5;
    int lane = threadIdx.x & 31;
    if (gw >= n) return;

    int   start = g_rowstart[gw];
    int   cnt   = g_deg[gw] - 1;
    float dv    = g_dinv[gw];

    float4 acc = *((const float4*)(g_bufA + (size_t)gw * 128) + lane);
    float  sc  = dv * dv;
    acc.x *= sc; acc.y *= sc; acc.z *= sc; acc.w *= sc;

    if (cnt > 0) {
        float2 e0 = g_edge[start];
        int    s0 = __float_as_int(e0.x);
        uint2  h0 = *((const uint2*)(g_bufA16 + (size_t)s0 * 64) + lane);
        for (int k = 1; k < cnt; k++) {
            float2 e1 = g_edge[start + k];          // prefetch next edge
            int    s1 = __float_as_int(e1.x);
            uint2  h1 = *((const uint2*)(g_bufA16 + (size_t)s1 * 64) + lane);
            float2 p0 = __half22float2(*(const __half2*)&h0.x);
            float2 p1 = __half22float2(*(const __half2*)&h0.y);
            acc.x = fmaf(e0.y, p0.x, acc.x);
            acc.y = fmaf(e0.y, p0.y, acc.y);
            acc.z = fmaf(e0.y, p1.x, acc.z);
            acc.w = fmaf(e0.y, p1.y, acc.w);
            e0 = e1; h0 = h1;
        }
        float2 p0 = __half22float2(*(const __half2*)&h0.x);
        float2 p1 = __half22float2(*(const __half2*)&h0.y);
        acc.x = fmaf(e0.y, p0.x, acc.x);
        acc.y = fmaf(e0.y, p0.y, acc.y);
        acc.z = fmaf(e0.y, p1.x, acc.z);
        acc.w = fmaf(e0.y, p1.y, acc.w);
    }

    float4 b = *((const float4*)bias + lane);
    acc.x += b.x; acc.y += b.y; acc.z += b.z; acc.w += b.w;

    if (do_prelu) {
        float al = aP[0];
        acc.x = acc.x > 0.f ? acc.x : al * acc.x;
        acc.y = acc.y > 0.f ? acc.y : al * acc.y;
        acc.z = acc.z > 0.f ? acc.z : al * acc.z;
        acc.w = acc.w > 0.f ? acc.w : al * acc.w;
    }
    *((float4*)(g_bufB + (size_t)gw * 128) + lane) = acc;
}

// ---------------- pooling ----------------
// 128 threads per block (one per feature); each block handles 256 nodes.
__global__ void k_pool_sum(const int* __restrict__ batch, int n) {
    int f  = threadIdx.x;                      // 0..127
    int n0 = blockIdx.x * 256;
    int n1 = min(n0 + 256, n);
    int gc = -1;
    float acc = 0.f;
    const float* H = g_bufB;
    for (int nn = n0; nn < n1; nn++) {
        int g = clampi(batch[nn], 0, G - 1);
        if (g != gc) {
            if (gc >= 0) atomicAdd(&g_gsum[gc * F + f], acc);
            acc = 0.f;
            gc = g;
        }
        acc += H[(size_t)nn * F + f];
    }
    if (gc >= 0) atomicAdd(&g_gsum[gc * F + f], acc);
}

__global__ void k_head(const float* __restrict__ linW, const float* __restrict__ linb,
                       float* __restrict__ out) {
    int t = blockIdx.x * blockDim.x + threadIdx.x;     // 640 outputs
    if (t >= G * OUTD) return;
    int g = t / OUTD;
    int o = t % OUTD;
    float c   = fmaxf((float)g_gcnt[g], 1.f);
    float inv = 1.f / c;
    float acc = 0.f;
#pragma unroll 8
    for (int h = 0; h < F; h++)
        acc = fmaf(g_gsum[g * F + h], linW[h * OUTD + o], acc);
    out[t] = acc * inv + linb[o];
}

// ---------------- launch ----------------
extern "C" void kernel_launch(void* const* d_in, const int* in_sizes, int n_in,
                              void* d_out, int out_size)
{
    // Resolve inputs BY SIZE (ordering-proof). Same-shaped tensors keep order.
    int iX = 0, iE = 0, iB = 0, iLW = 0, iLb = 0;
    int iW[3] = {0, 0, 0}, ib[3] = {0, 0, 0}, ia[2] = {0, 0};
    int nW = 0, nb = 0, na = 0;
    for (int i = 0; i < n_in; i++) {
        int s = in_sizes[i];
        if      (s == NMAX * F)   iX = i;
        else if (s == 2 * EMAX)   iE = i;
        else if (s == NMAX)       iB = i;
        else if (s == F * F)      { if (nW < 3) iW[nW++] = i; }
        else if (s == F)          { if (nb < 3) ib[nb++] = i; }
        else if (s == 1)          { if (na < 2) ia[na++] = i; }
        else if (s == F * OUTD)   iLW = i;
        else if (s == OUTD)       iLb = i;
    }

    const float* x    = (const float*)d_in[iX];
    const int*   ei   = (const int*)d_in[iE];    // int32 (JAX x64 disabled)
    const int*   bat  = (const int*)d_in[iB];
    const float* W0   = (const float*)d_in[iW[0]];
    const float* b0   = (const float*)d_in[ib[0]];
    const float* a0   = (const float*)d_in[ia[0]];
    const float* W1   = (const float*)d_in[iW[1]];
    const float* b1   = (const float*)d_in[ib[1]];
    const float* a1   = (const float*)d_in[ia[1]];
    const float* W2   = (const float*)d_in[iW[2]];
    const float* b2   = (const float*)d_in[ib[2]];
    const float* linW = (const float*)d_in[iLW];
    const float* linb = (const float*)d_in[iLb];
    float*       out  = (float*)d_out;

    int n = in_sizes[iX] / F;       // 100000
    int e = in_sizes[iE] / 2;       // 1600000
    const int* src = ei;
    const int* dst = ei + e;

    int nscan       = (n + 1023) / 1024;            // 98
    int gemm_blocks = (n + 127) / 128;
    int agg_blocks  = (n * 32 + 255) / 256;         // warp per node

    // launch index:                                              v
    k_deg_init <<<(n + 255) / 256, 256>>>(n);                  // 0
    k_deg_count<<<(e + 255) / 256, 256>>>(dst, e, n);          // 1
    k_scan1    <<<nscan, 1024>>>(n);                           // 2 (+dinv)
    k_gemm_tf32<<<gemm_blocks, 256>>>(x, 1, W0, n);            // 3  <-- ncu capture slot
    k_scan2    <<<1, 128>>>(nscan, bat, n);                    // 4 (+pool_init)
    k_scan3    <<<(n + 255) / 256, 256>>>(n);                  // 5
    k_csr_fill <<<(e + 255) / 256, 256>>>(src, dst, e, n);     // 6

    k_aggregate<<<agg_blocks, 256>>>(b0, a0, n, 1);            // 7
    k_gemm_tf32<<<gemm_blocks, 256>>>(nullptr, 0, W1, n);      // 8
    k_aggregate<<<agg_blocks, 256>>>(b1, a1, n, 1);            // 9
    k_gemm_tf32<<<gemm_blocks, 256>>>(nullptr, 0, W2, n);      // 10
    k_aggregate<<<agg_blocks, 256>>>(b2, nullptr, n, 0);       // 11

    k_pool_sum<<<(n + 255) / 256, 128>>>(bat, n);              // 12
    k_head<<<3, 256>>>(linW, linb, out);                       // 13
}

// round 12
// speedup vs baseline: 1.3866x; 1.2581x over previous
#include <cuda_runtime.h>
#include <cuda_bf16.h>
#include <cuda_fp16.h>
#include <math.h>
#include <stdint.h>

// Problem constants (fixed by the dataset)
#define NMAX 100000
#define EMAX 1600000
#define F    128
#define G    64
#define OUTD 10

// ---------------- device scratch (static, no allocation) ----------------
__device__ float   g_bufA[(size_t)NMAX * F];    // GEMM output h (fp32, self term)
__device__ __half2 g_bufA16[(size_t)NMAX * 64]; // GEMM output h (fp16, gathers)
__device__ float   g_bufB[(size_t)NMAX * F];    // layer output (fp32, pool/self)
__device__ __half2 g_bufB16[(size_t)NMAX * 64]; // layer output (fp16, next GEMM A)
__device__ __half2 g_x16[(size_t)NMAX * 64];    // x converted to fp16 (layer-1 A)
__device__ float   g_dinv[NMAX];
__device__ int     g_deg[NMAX];                 // degree incl. self loop
__device__ int     g_scan[NMAX];
__device__ int     g_bsum[128];
__device__ int     g_rowstart[NMAX];
__device__ int     g_pos[NMAX];
__device__ float2  g_edge[EMAX];                // packed (src as int bits, norm)
__device__ float   g_gsum[G * F];
__device__ int     g_gcnt[G];

__device__ __forceinline__ int clampi(int v, int lo, int hi) {
    return v < lo ? lo : (v > hi ? hi : v);
}

__device__ __forceinline__ void mma_f16(float* c, const uint32_t* a,
                                        uint32_t b0, uint32_t b1) {
    asm volatile(
        "mma.sync.aligned.m16n8k16.row.col.f32.f16.f16.f32 "
        "{%0,%1,%2,%3},{%4,%5,%6,%7},{%8,%9},{%0,%1,%2,%3};"
        : "+f"(c[0]), "+f"(c[1]), "+f"(c[2]), "+f"(c[3])
        : "r"(a[0]), "r"(a[1]), "r"(a[2]), "r"(a[3]), "r"(b0), "r"(b1));
}

// ---------------- degree ----------------
__global__ void k_deg_init(int n) {
    int i = blockIdx.x * blockDim.x + threadIdx.x;
    if (i < n) g_deg[i] = 1;            // self loop contributes 1
}

__global__ void k_deg_count(const int* __restrict__ dst, int e, int n) {
    int i = blockIdx.x * blockDim.x + threadIdx.x;
    if (i < e) atomicAdd(&g_deg[clampi(dst[i], 0, n - 1)], 1);
}

// ---------------- x -> fp16 ----------------
__global__ void k_x16(const float* __restrict__ x, int n) {
    int i = blockIdx.x * blockDim.x + threadIdx.x;   // half2 units: n*64
    if (i < n * 64) {
        float2 v = ((const float2*)x)[i];
        g_x16[i] = __float22half2_rn(v);
    }
}

// ---------------- scan1 (+dinv fused) ----------------
__global__ void k_scan1(int n) {                 // 1024 threads/block
    __shared__ int sh[1024];
    int gid = blockIdx.x * 1024 + threadIdx.x;
    int deg = (gid < n) ? g_deg[gid] : 1;
    if (gid < n) g_dinv[gid] = rsqrtf((float)deg);
    int v = (gid < n) ? (deg - 1) : 0;
    sh[threadIdx.x] = v;
    __syncthreads();
    for (int off = 1; off < 1024; off <<= 1) {   // Hillis-Steele inclusive
        int t = (threadIdx.x >= off) ? sh[threadIdx.x - off] : 0;
        __syncthreads();
        sh[threadIdx.x] += t;
        __syncthreads();
    }
    if (gid < n) g_scan[gid] = sh[threadIdx.x];
    if (threadIdx.x == 1023) g_bsum[blockIdx.x] = sh[1023];
}

// ---------------- scan2 (+pool_init fused) ----------------
__global__ void k_scan2(int nb, const int* __restrict__ batch, int n) {  // 1 block, 128 thr
    __shared__ int sh[128];
    int t = threadIdx.x;
    sh[t] = (t < nb) ? g_bsum[t] : 0;
    __syncthreads();
    if (t == 0) {
        int acc = 0;
        for (int i = 0; i < nb; i++) { int v = sh[i]; sh[i] = acc; acc += v; }
    }
    __syncthreads();
    if (t < nb) g_bsum[t] = sh[t];

    // pool init
    for (int i = t; i < G * F; i += blockDim.x) g_gsum[i] = 0.f;
    if (t < G) {
        int lo, hi;
        {
            int a = 0, b = n;
            while (a < b) { int m = (a + b) >> 1; if (batch[m] < t) a = m + 1; else b = m; }
            lo = a;
        }
        {
            int a = 0, b = n;
            while (a < b) { int m = (a + b) >> 1; if (batch[m] < t + 1) a = m + 1; else b = m; }
            hi = a;
        }
        g_gcnt[t] = hi - lo;
    }
}

__global__ void k_scan3(int n) {
    int gid = blockIdx.x * blockDim.x + threadIdx.x;
    if (gid >= n) return;
    int cnt   = g_deg[gid] - 1;
    int start = g_scan[gid] - cnt + g_bsum[gid >> 10];   // exclusive start
    g_rowstart[gid] = start;
    g_pos[gid]      = start;
}

__global__ void k_csr_fill(const int* __restrict__ src, const int* __restrict__ dst,
                           int e, int n) {
    int i = blockIdx.x * blockDim.x + threadIdx.x;
    if (i >= e) return;
    int s = clampi(src[i], 0, n - 1);
    int d = clampi(dst[i], 0, n - 1);
    int slot = atomicAdd(&g_pos[d], 1);
    g_edge[slot] = make_float2(__int_as_float(s), g_dinv[s] * g_dinv[d]);
}

// ---------------- fp16 tensor-core GEMM, W split hi+lo (2 mmas) ----------------
// g_bufA[n x 128] = X[n x 128] @ W[128 x 128]; writes fp32 + fp16 copies.
// Single K pass: full A tile (128x128 fp16) + full W ({hi,lo} fp16 pairs) in smem.
// Block: 256 threads (8 warps), tile 128 rows; warp tile 32x64.
#define GAS 68   // half2 per A row (64 + 4 pad)
#define GWS 68   // uint2 per WP row (64 + 4 pad)
#define GEMM_SMEM (128 * GAS * 4 + 128 * GWS * 8)   // 34816 + 69632 = 104448 B
__global__ __launch_bounds__(256, 2) void k_gemm_f16(
    int use_ext, const float* __restrict__ W, int nrows)
{
    extern __shared__ char sm_[];
    __half2* A2 = (__half2*)sm_;                      // [128][GAS]  A[m][k-pair]
    uint2*   WP = (uint2*)(sm_ + 128 * GAS * 4);      // [128][GWS]  per n: {hi2,lo2}(k-pair)

    const __half2* Xsrc = use_ext ? g_x16 : g_bufB16;

    int tid  = threadIdx.x;
    int row0 = blockIdx.x * 128;

    // ---- fill A tile: straight fp16 copy (coalesced 16B chunks) ----
#pragma unroll
    for (int i = 0; i < 8; i++) {
        int c  = tid + i * 256;        // 0..2047 chunks of 4 half2
        int m  = c >> 4;               // 0..127
        int kq = (c & 15) * 4;         // half2 col 0,4,..60
        uint4 v = make_uint4(0u, 0u, 0u, 0u);
        int row = row0 + m;
        if (row < nrows) v = *(const uint4*)(Xsrc + (size_t)row * 64 + kq);
        *(uint4*)(A2 + m * GAS + kq) = v;
    }
    // ---- fill WP: W[k][n] -> per-n k-pairs, split hi/lo ----
#pragma unroll
    for (int i = 0; i < 32; i++) {
        int e  = tid + i * 256;        // 0..8191
        int kc = e >> 7;               // k-pair 0..63
        int nn = e & 127;
        float w0 = W[(2 * kc) * 128 + nn];
        float w1 = W[(2 * kc + 1) * 128 + nn];
        __half h0 = __float2half_rn(w0);
        __half h1 = __float2half_rn(w1);
        __half l0 = __float2half_rn(w0 - __half2float(h0));
        __half l1 = __float2half_rn(w1 - __half2float(h1));
        __half2 hp = __halves2half2(h0, h1);
        __half2 lp = __halves2half2(l0, l1);
        uint2 q;
        q.x = *(uint32_t*)&hp;
        q.y = *(uint32_t*)&lp;
        WP[nn * GWS + kc] = q;
    }
    __syncthreads();

    int lane = tid & 31;
    int wid  = tid >> 5;
    int g    = lane >> 2;          // 0..7
    int t    = lane & 3;           // 0..3
    int wm   = (wid & 3) * 32;     // warp m offset
    int wn   = (wid >> 2) * 64;    // warp n offset

    float acc[2][8][4];
#pragma unroll
    for (int mi = 0; mi < 2; mi++)
#pragma unroll
        for (int ni = 0; ni < 8; ni++)
#pragma unroll
            for (int q = 0; q < 4; q++) acc[mi][ni][q] = 0.f;

#pragma unroll
    for (int kk = 0; kk < 8; kk++) {           // k16 steps over K=128
        int kb = kk * 8;                       // k-pair base
        uint32_t a[2][4];
#pragma unroll
        for (int mi = 0; mi < 2; mi++) {
            int m = wm + mi * 16;
            a[mi][0] = *(uint32_t*)&A2[(m + g)     * GAS + kb + t];
            a[mi][1] = *(uint32_t*)&A2[(m + g + 8) * GAS + kb + t];
            a[mi][2] = *(uint32_t*)&A2[(m + g)     * GAS + kb + 4 + t];
            a[mi][3] = *(uint32_t*)&A2[(m + g + 8) * GAS + kb + 4 + t];
        }
#pragma unroll
        for (int ni = 0; ni < 8; ni++) {
            int nn = wn + ni * 8 + g;
            uint2 q0 = WP[nn * GWS + kb + t];        // {b0_hi, b0_lo}
            uint2 q1 = WP[nn * GWS + kb + 4 + t];    // {b1_hi, b1_lo}
#pragma unroll
            for (int mi = 0; mi < 2; mi++) {
                mma_f16(acc[mi][ni], a[mi], q0.x, q1.x);   // A * W_hi
                mma_f16(acc[mi][ni], a[mi], q0.y, q1.y);   // A * W_lo
            }
        }
    }

    // ---- write C fragments (fp32 + fp16 copy) ----
#pragma unroll
    for (int mi = 0; mi < 2; mi++) {
#pragma unroll
        for (int ni = 0; ni < 8; ni++) {
            int col = wn + ni * 8 + t * 2;
            int r0  = row0 + wm + mi * 16 + g;
            int r1  = r0 + 8;
            float2 v0 = make_float2(acc[mi][ni][0], acc[mi][ni][1]);
            float2 v1 = make_float2(acc[mi][ni][2], acc[mi][ni][3]);
            if (r0 < nrows) {
                *(float2*)(g_bufA + (size_t)r0 * 128 + col) = v0;
                g_bufA16[(size_t)r0 * 64 + (col >> 1)] = __float22half2_rn(v0);
            }
            if (r1 < nrows) {
                *(float2*)(g_bufA + (size_t)r1 * 128 + col) = v1;
                g_bufA16[(size_t)r1 * 64 + (col >> 1)] = __float22half2_rn(v1);
            }
        }
    }
}

// ---- fused aggregate: bufB[d] = prelu(dinv2*bufA[d] + sum norm*h16[s] + bias) ----
// Warp per dst node; lane owns 4 features. Self term fp32, gathers fp16.
// Also writes fp16 copy of the output (A operand of the next GEMM).
__global__ void k_aggregate(const float* __restrict__ bias,
                            const float* __restrict__ aP, int n, int do_prelu)
{
    int gw   = (blockIdx.x * blockDim.x + threadIdx.x) >> 5;
    int lane = threadIdx.x & 31;
    if (gw >= n) return;

    int   start = g_rowstart[gw];
    int   cnt   = g_deg[gw] - 1;
    float dv    = g_dinv[gw];

    float4 acc = *((const float4*)(g_bufA + (size_t)gw * 128) + lane);
    float  sc  = dv * dv;
    acc.x *= sc; acc.y *= sc; acc.z *= sc; acc.w *= sc;

    if (cnt > 0) {
        float2 e0 = g_edge[start];
        int    s0 = __float_as_int(e0.x);
        uint2  h0 = *((const uint2*)(g_bufA16 + (size_t)s0 * 64) + lane);
        for (int k = 1; k < cnt; k++) {
            float2 e1 = g_edge[start + k];          // prefetch next edge
            int    s1 = __float_as_int(e1.x);
            uint2  h1 = *((const uint2*)(g_bufA16 + (size_t)s1 * 64) + lane);
            float2 p0 = __half22float2(*(const __half2*)&h0.x);
            float2 p1 = __half22float2(*(const __half2*)&h0.y);
            acc.x = fmaf(e0.y, p0.x, acc.x);
            acc.y = fmaf(e0.y, p0.y, acc.y);
            acc.z = fmaf(e0.y, p1.x, acc.z);
            acc.w = fmaf(e0.y, p1.y, acc.w);
            e0 = e1; h0 = h1;
        }
        float2 p0 = __half22float2(*(const __half2*)&h0.x);
        float2 p1 = __half22float2(*(const __half2*)&h0.y);
        acc.x = fmaf(e0.y, p0.x, acc.x);
        acc.y = fmaf(e0.y, p0.y, acc.y);
        acc.z = fmaf(e0.y, p1.x, acc.z);
        acc.w = fmaf(e0.y, p1.y, acc.w);
    }

    float4 b = *((const float4*)bias + lane);
    acc.x += b.x; acc.y += b.y; acc.z += b.z; acc.w += b.w;

    if (do_prelu) {
        float al = aP[0];
        acc.x = acc.x > 0.f ? acc.x : al * acc.x;
        acc.y = acc.y > 0.f ? acc.y : al * acc.y;
        acc.z = acc.z > 0.f ? acc.z : al * acc.z;
        acc.w = acc.w > 0.f ? acc.w : al * acc.w;
    }
    *((float4*)(g_bufB + (size_t)gw * 128) + lane) = acc;

    __half2 o0 = __float22half2_rn(make_float2(acc.x, acc.y));
    __half2 o1 = __float22half2_rn(make_float2(acc.z, acc.w));
    uint2 ov;
    ov.x = *(uint32_t*)&o0;
    ov.y = *(uint32_t*)&o1;
    *((uint2*)(g_bufB16 + (size_t)gw * 64) + lane) = ov;
}

// ---------------- pooling ----------------
// 128 threads per block (one per feature); each block handles 256 nodes.
__global__ void k_pool_sum(const int* __restrict__ batch, int n) {
    int f  = threadIdx.x;                      // 0..127
    int n0 = blockIdx.x * 256;
    int n1 = min(n0 + 256, n);
    int gc = -1;
    float acc = 0.f;
    const float* H = g_bufB;
    for (int nn = n0; nn < n1; nn++) {
        int g = clampi(batch[nn], 0, G - 1);
        if (g != gc) {
            if (gc >= 0) atomicAdd(&g_gsum[gc * F + f], acc);
            acc = 0.f;
            gc = g;
        }
        acc += H[(size_t)nn * F + f];
    }
    if (gc >= 0) atomicAdd(&g_gsum[gc * F + f], acc);
}

__global__ void k_head(const float* __restrict__ linW, const float* __restrict__ linb,
                       float* __restrict__ out) {
    int t = blockIdx.x * blockDim.x + threadIdx.x;     // 640 outputs
    if (t >= G * OUTD) return;
    int g = t / OUTD;
    int o = t % OUTD;
    float c   = fmaxf((float)g_gcnt[g], 1.f);
    float inv = 1.f / c;
    float acc = 0.f;
#pragma unroll 8
    for (int h = 0; h < F; h++)
        acc = fmaf(g_gsum[g * F + h], linW[h * OUTD + o], acc);
    out[t] = acc * inv + linb[o];
}

// ---------------- launch ----------------
extern "C" void kernel_launch(void* const* d_in, const int* in_sizes, int n_in,
                              void* d_out, int out_size)
{
    // Resolve inputs BY SIZE (ordering-proof). Same-shaped tensors keep order.
    int iX = 0, iE = 0, iB = 0, iLW = 0, iLb = 0;
    int iW[3] = {0, 0, 0}, ib[3] = {0, 0, 0}, ia[2] = {0, 0};
    int nW = 0, nb = 0, na = 0;
    for (int i = 0; i < n_in; i++) {
        int s = in_sizes[i];
        if      (s == NMAX * F)   iX = i;
        else if (s == 2 * EMAX)   iE = i;
        else if (s == NMAX)       iB = i;
        else if (s == F * F)      { if (nW < 3) iW[nW++] = i; }
        else if (s == F)          { if (nb < 3) ib[nb++] = i; }
        else if (s == 1)          { if (na < 2) ia[na++] = i; }
        else if (s == F * OUTD)   iLW = i;
        else if (s == OUTD)       iLb = i;
    }

    const float* x    = (const float*)d_in[iX];
    const int*   ei   = (const int*)d_in[iE];    // int32 (JAX x64 disabled)
    const int*   bat  = (const int*)d_in[iB];
    const float* W0   = (const float*)d_in[iW[0]];
    const float* b0   = (const float*)d_in[ib[0]];
    const float* a0   = (const float*)d_in[ia[0]];
    const float* W1   = (const float*)d_in[iW[1]];
    const float* b1   = (const float*)d_in[ib[1]];
    const float* a1   = (const float*)d_in[ia[1]];
    const float* W2   = (const float*)d_in[iW[2]];
    const float* b2   = (const float*)d_in[ib[2]];
    const float* linW = (const float*)d_in[iLW];
    const float* linb = (const float*)d_in[iLb];
    float*       out  = (float*)d_out;

    int n = in_sizes[iX] / F;       // 100000
    int e = in_sizes[iE] / 2;       // 1600000
    const int* src = ei;
    const int* dst = ei + e;

    static int smem_set = 0;
    if (!smem_set) {
        cudaFuncSetAttribute(k_gemm_f16,
                             cudaFuncAttributeMaxDynamicSharedMemorySize, GEMM_SMEM);
        smem_set = 1;
    }

    int nscan       = (n + 1023) / 1024;            // 98
    int gemm_blocks = (n + 127) / 128;
    int agg_blocks  = (n * 32 + 255) / 256;         // warp per node
    int x16_blocks  = (n * 64 + 255) / 256;

    // launch index:                                                     v
    k_deg_init <<<(n + 255) / 256, 256>>>(n);                         // 0
    k_deg_count<<<(e + 255) / 256, 256>>>(dst, e, n);                 // 1
    k_x16      <<<x16_blocks, 256>>>(x, n);                           // 2
    k_gemm_f16 <<<gemm_blocks, 256, GEMM_SMEM>>>(1, W0, n);           // 3  <-- ncu slot
    k_scan1    <<<nscan, 1024>>>(n);                                  // 4 (+dinv)
    k_scan2    <<<1, 128>>>(nscan, bat, n);                           // 5 (+pool_init)
    k_scan3    <<<(n + 255) / 256, 256>>>(n);                         // 6
    k_csr_fill <<<(e + 255) / 256, 256>>>(src, dst, e, n);            // 7

    k_aggregate<<<agg_blocks, 256>>>(b0, a0, n, 1);                   // 8
    k_gemm_f16 <<<gemm_blocks, 256, GEMM_SMEM>>>(0, W1, n);           // 9
    k_aggregate<<<agg_blocks, 256>>>(b1, a1, n, 1);                   // 10
    k_gemm_f16 <<<gemm_blocks, 256, GEMM_SMEM>>>(0, W2, n);           // 11
    k_aggregate<<<agg_blocks, 256>>>(b2, nullptr, n, 0);              // 12

    k_pool_sum<<<(n + 255) / 256, 128>>>(bat, n);                     // 13
    k_head<<<3, 256>>>(linW, linb, out);                              // 14
}